// round 16
// baseline (speedup 1.0000x reference)
#include <cuda_runtime.h>
#include <cuda_bf16.h>
#include <cstdint>

#define SEQ    2048
#define DM     1024
#define NH     16
#define HD     64
#define BATCH  4
#define BHN    (BATCH * NH)      // 64
#define TOK    (BATCH * SEQ)     // 8192
#define KVN    ((size_t)BHN * SEQ * HD)

// fp32 scratch
__device__ float g_Q [KVN];
__device__ float g_AO[KVN];
// bf16 hi/lo scratch (written directly by projection epilogues)
__device__ __nv_bfloat16 g_Kh [KVN];   // [bh][s][d]
__device__ __nv_bfloat16 g_Kl [KVN];
__device__ __nv_bfloat16 g_Vth[KVN];   // [bh][d][s]
__device__ __nv_bfloat16 g_Vtl[KVN];

__device__ __forceinline__ uint32_t f2tf32(float x) {
    uint32_t u;
    asm volatile("cvt.rna.tf32.f32 %0, %1;" : "=r"(u) : "f"(x));
    return u;
}

__device__ __forceinline__ void mma_tf32(float c[4], const uint32_t a[4], const uint32_t b[2]) {
    asm volatile(
        "mma.sync.aligned.m16n8k8.row.col.f32.tf32.tf32.f32 "
        "{%0,%1,%2,%3}, {%4,%5,%6,%7}, {%8,%9}, {%0,%1,%2,%3};"
        : "+f"(c[0]), "+f"(c[1]), "+f"(c[2]), "+f"(c[3])
        : "r"(a[0]), "r"(a[1]), "r"(a[2]), "r"(a[3]), "r"(b[0]), "r"(b[1]));
}

__device__ __forceinline__ void mma_bf16(float c[4], const uint32_t a[4],
                                         uint32_t b0, uint32_t b1) {
    asm volatile(
        "mma.sync.aligned.m16n8k16.row.col.f32.bf16.bf16.f32 "
        "{%0,%1,%2,%3}, {%4,%5,%6,%7}, {%8,%9}, {%0,%1,%2,%3};"
        : "+f"(c[0]), "+f"(c[1]), "+f"(c[2]), "+f"(c[3])
        : "r"(a[0]), "r"(a[1]), "r"(a[2]), "r"(a[3]), "r"(b0), "r"(b1));
}

__device__ __forceinline__ void ldsm4(uint32_t r[4], uint32_t saddr) {
    asm volatile("ldmatrix.sync.aligned.m8n8.x4.shared.b16 {%0,%1,%2,%3}, [%4];"
                 : "=r"(r[0]), "=r"(r[1]), "=r"(r[2]), "=r"(r[3]) : "r"(saddr));
}

// split two floats into packed bf16x2 hi and lo
__device__ __forceinline__ void split2(float x, float y, uint32_t& hi, uint32_t& lo) {
    __nv_bfloat16 hx = __float2bfloat16(x), hy = __float2bfloat16(y);
    __nv_bfloat162 hp = __halves2bfloat162(hx, hy);
    hi = *(uint32_t*)&hp;
    __nv_bfloat16 lx = __float2bfloat16(x - __bfloat162float(hx));
    __nv_bfloat16 ly = __float2bfloat16(y - __bfloat162float(hy));
    __nv_bfloat162 lp = __halves2bfloat162(lx, ly);
    lo = *(uint32_t*)&lp;
}

__device__ __forceinline__ void splitbf(float x, __nv_bfloat16& h, __nv_bfloat16& l) {
    h = __float2bfloat16(x);
    l = __float2bfloat16(x - __bfloat162float(h));
}

__device__ __forceinline__ void cp16(void* dst, const void* src) {
    asm volatile("cp.async.cg.shared.global [%0], [%1], 16;"
                 :: "r"((uint32_t)__cvta_generic_to_shared(dst)), "l"(src));
}
__device__ __forceinline__ void cp_commit() {
    asm volatile("cp.async.commit_group;");
}
template<int N>
__device__ __forceinline__ void cp_wait() {
    asm volatile("cp.async.wait_group %0;" :: "n"(N));
}

// ---------------------------------------------------------------------------
// tf32 tensor-core GEMM with permuted-k smem layout.
// Within each k8 group, elements are stored in order [0,4,1,5,2,6,3,7] so a
// thread's fragment pair (k+tig, k+tig+4) is one aligned LDS.64.
// AMODE 0: A row-major.  AMODE 1: A gathered from [B,H,S,hd].
// OMODE 0: C row-major fp32.      OMODE 1: C scattered fp32 [B,H,S,hd].
// OMODE 2: bf16 hi/lo to Ch/Cl in [bh][s][d]   (K projection).
// OMODE 3: bf16 hi/lo to Ch/Cl in [bh][d][s]   (V projection, transposed).
// ---------------------------------------------------------------------------
#define BK   32
#define LDA  36

template<int AMODE, int OMODE>
__global__ __launch_bounds__(256)
void tgemm_kernel(const float* __restrict__ A, const float* __restrict__ W,
                  const float* __restrict__ bias, float* __restrict__ C,
                  __nv_bfloat16* __restrict__ Ch, __nv_bfloat16* __restrict__ Cl,
                  int M, int N, int K)
{
    __shared__ float As[128 * LDA];
    __shared__ float Bs[128 * LDA];

    const int tid  = threadIdx.x;
    const int lane = tid & 31;
    const int warp = tid >> 5;
    const int grp  = lane >> 2;
    const int tig  = lane & 3;
    const int wm   = warp & 1;
    const int wn   = warp >> 1;
    const int rowBase = blockIdx.y * 128;
    const int colBase = blockIdx.x * 128;

    const int lrow = tid >> 3;
    const int lk   = (tid & 7) * 4;
    // permuted store base: group base + odd offset for upper-half chunks
    const int pbase = (lk & 24) + ((lk & 4) ? 1 : 0);

    float acc[4][4][4];
#pragma unroll
    for (int i = 0; i < 4; i++)
#pragma unroll
        for (int j = 0; j < 4; j++)
#pragma unroll
            for (int c = 0; c < 4; c++) acc[i][j][c] = 0.f;

    float4 aReg[4], bReg[4];

    auto fetch = [&](int k0) {
#pragma unroll
        for (int p = 0; p < 4; p++) {
            const int r = lrow + p * 32;
            const int kk = k0 + lk;
            const float* ap;
            if (AMODE == 0) {
                ap = A + (size_t)(rowBase + r) * K + kk;
            } else {
                const int m = rowBase + r;
                const int b = m >> 11, s = m & 2047;
                const int h = kk >> 6, d = kk & 63;
                ap = A + (((size_t)(b * NH + h) * SEQ + s) << 6) + d;
            }
            aReg[p] = *(const float4*)ap;
            bReg[p] = *(const float4*)(W + (size_t)(colBase + r) * K + kk);
        }
    };

    auto stage = [&]() {
#pragma unroll
        for (int p = 0; p < 4; p++) {
            const int r = lrow + p * 32;
            // permuted positions: pbase + {0,2,4,6}
            As[r * LDA + pbase + 0] = __uint_as_float(f2tf32(aReg[p].x));
            As[r * LDA + pbase + 2] = __uint_as_float(f2tf32(aReg[p].y));
            As[r * LDA + pbase + 4] = __uint_as_float(f2tf32(aReg[p].z));
            As[r * LDA + pbase + 6] = __uint_as_float(f2tf32(aReg[p].w));
            Bs[r * LDA + pbase + 0] = __uint_as_float(f2tf32(bReg[p].x));
            Bs[r * LDA + pbase + 2] = __uint_as_float(f2tf32(bReg[p].y));
            Bs[r * LDA + pbase + 4] = __uint_as_float(f2tf32(bReg[p].z));
            Bs[r * LDA + pbase + 6] = __uint_as_float(f2tf32(bReg[p].w));
        }
    };

    fetch(0);
    const int ntile = K / BK;
    for (int t = 0; t < ntile; t++) {
        __syncthreads();
        stage();
        __syncthreads();
        if (t + 1 < ntile) fetch((t + 1) * BK);

#pragma unroll
        for (int ks = 0; ks < 4; ks++) {
            const int k = ks * 8;        // group base (same in permuted space)
            uint32_t af[4][4], bf[4][2];
#pragma unroll
            for (int mt = 0; mt < 4; mt++) {
                const int m0 = wm * 64 + mt * 16;
                // LDS.64: {k+tig, k+tig+4} adjacent at permuted offset 2*tig
                float2 a01 = *(const float2*)&As[(m0 + grp)     * LDA + k + 2 * tig];
                float2 a23 = *(const float2*)&As[(m0 + grp + 8) * LDA + k + 2 * tig];
                af[mt][0] = __float_as_uint(a01.x);
                af[mt][1] = __float_as_uint(a23.x);
                af[mt][2] = __float_as_uint(a01.y);
                af[mt][3] = __float_as_uint(a23.y);
            }
#pragma unroll
            for (int nt = 0; nt < 4; nt++) {
                const int n0 = wn * 32 + nt * 8;
                float2 b01 = *(const float2*)&Bs[(n0 + grp) * LDA + k + 2 * tig];
                bf[nt][0] = __float_as_uint(b01.x);
                bf[nt][1] = __float_as_uint(b01.y);
            }
#pragma unroll
            for (int mt = 0; mt < 4; mt++)
#pragma unroll
                for (int nt = 0; nt < 4; nt++)
                    mma_tf32(acc[mt][nt], af[mt], bf[nt]);
        }
    }

#pragma unroll
    for (int mt = 0; mt < 4; mt++) {
#pragma unroll
        for (int half = 0; half < 2; half++) {
            const int m = rowBase + wm * 64 + mt * 16 + grp + half * 8;
            const int b = m >> 11, s = m & 2047;
#pragma unroll
            for (int nt = 0; nt < 4; nt++) {
                const int n = colBase + wn * 32 + nt * 8 + 2 * tig;
                float2 r;
                r.x = acc[mt][nt][half * 2 + 0] + bias[n + 0];
                r.y = acc[mt][nt][half * 2 + 1] + bias[n + 1];
                const int h = n >> 6, d = n & 63;
                if (OMODE == 0) {
                    *(float2*)(C + (size_t)m * N + n) = r;
                } else if (OMODE == 1) {
                    *(float2*)(C + (((size_t)(b * NH + h) * SEQ + s) << 6) + d) = r;
                } else if (OMODE == 2) {
                    const size_t o = (((size_t)(b * NH + h) * SEQ + s) << 6) + d;
                    __nv_bfloat16 hx, lx, hy, ly;
                    splitbf(r.x, hx, lx); splitbf(r.y, hy, ly);
                    __nv_bfloat162 hp = __halves2bfloat162(hx, hy);
                    __nv_bfloat162 lp = __halves2bfloat162(lx, ly);
                    *(__nv_bfloat162*)&Ch[o] = hp;
                    *(__nv_bfloat162*)&Cl[o] = lp;
                } else {
                    const size_t o = ((size_t)(b * NH + h) * HD + d) * SEQ + s;
                    __nv_bfloat16 hx, lx, hy, ly;
                    splitbf(r.x, hx, lx); splitbf(r.y, hy, ly);
                    Ch[o] = hx;       Cl[o] = lx;
                    Ch[o + SEQ] = hy; Cl[o + SEQ] = ly;
                }
            }
        }
    }
}

// ---------------------------------------------------------------------------
// bf16 flash attention (proven R10 version, unchanged)
// ---------------------------------------------------------------------------
#define TLD   72
#define TBUF  (64 * TLD)
#define TBUF2 (TBUF * 2)
#define ATTN_SMEM_BYTES (8 * TBUF2)   // 73728 B

__global__ __launch_bounds__(128, 3)
void attn_bf16_kernel(const float* __restrict__ Qg,
                      const __nv_bfloat16* __restrict__ Khg,
                      const __nv_bfloat16* __restrict__ Klg,
                      const __nv_bfloat16* __restrict__ Vthg,
                      const __nv_bfloat16* __restrict__ Vtlg,
                      float* __restrict__ Og)
{
    extern __shared__ __nv_bfloat16 smem[];

    const int tid  = threadIdx.x;
    const int lane = tid & 31;
    const int warp = tid >> 5;
    const int grp  = lane >> 2;
    const int tig  = lane & 3;
    const int m0   = warp * 16;
    const int bh   = blockIdx.y;
    const int q0   = blockIdx.x * 64;

    const float* Qb = Qg + ((size_t)bh * SEQ + q0) * HD;
    const size_t kbase = (size_t)bh * SEQ * HD;
    const size_t vbase = (size_t)bh * HD * SEQ;

    __nv_bfloat16* KhS[2] = { smem + 0 * TBUF, smem + 1 * TBUF };
    __nv_bfloat16* KlS[2] = { smem + 2 * TBUF, smem + 3 * TBUF };
    __nv_bfloat16* VhS[2] = { smem + 4 * TBUF, smem + 5 * TBUF };
    __nv_bfloat16* VlS[2] = { smem + 6 * TBUF, smem + 7 * TBUF };

    const uint32_t sb = (uint32_t)__cvta_generic_to_shared(smem);

    const int mi = lane >> 3, mr = lane & 7;
    uint32_t lrow[4];
#pragma unroll
    for (int npb = 0; npb < 4; npb++)
        lrow[npb] = (uint32_t)(((npb * 16 + (mi >> 1) * 8 + mr) * TLD) * 2 + (mi & 1) * 16);

    auto prefetch = [&](int t, int buf) {
        const size_t ko = kbase + (size_t)t * 64 * HD;
        const size_t vo = vbase + (size_t)t * 64;
        for (int i = tid; i < 512; i += 128) {
            const int r = i >> 3, c = (i & 7) * 8;
            cp16(KhS[buf] + r * TLD + c, Khg  + ko + (size_t)r * HD + c);
            cp16(KlS[buf] + r * TLD + c, Klg  + ko + (size_t)r * HD + c);
            cp16(VhS[buf] + r * TLD + c, Vthg + vo + (size_t)r * SEQ + c);
            cp16(VlS[buf] + r * TLD + c, Vtlg + vo + (size_t)r * SEQ + c);
        }
    };

    prefetch(0, 0);
    cp_commit();

    uint32_t qh[4][4], ql[4][4];
#pragma unroll
    for (int ks = 0; ks < 4; ks++) {
#pragma unroll
        for (int p = 0; p < 2; p++) {
            const int kcol = 16 * ks + 2 * tig + 8 * p;
            float2 x0 = *(const float2*)(Qb + (size_t)(m0 + grp)     * HD + kcol);
            float2 x1 = *(const float2*)(Qb + (size_t)(m0 + grp + 8) * HD + kcol);
            split2(0.125f * x0.x, 0.125f * x0.y, qh[ks][2 * p],     ql[ks][2 * p]);
            split2(0.125f * x1.x, 0.125f * x1.y, qh[ks][2 * p + 1], ql[ks][2 * p + 1]);
        }
    }

    float o[8][4];
    float mi2[2], li[2];
    mi2[0] = mi2[1] = -1e30f; li[0] = li[1] = 0.f;
#pragma unroll
    for (int nt = 0; nt < 8; nt++)
#pragma unroll
        for (int c = 0; c < 4; c++) o[nt][c] = 0.f;

    const int NT = SEQ / 64;
    for (int t = 0; t < NT; t++) {
        const int cur = t & 1;
        if (t + 1 < NT) {
            prefetch(t + 1, 1 - cur);
            cp_commit();
            cp_wait<1>();
        } else {
            cp_wait<0>();
        }
        __syncthreads();

        const uint32_t khA = sb + (0 + cur) * TBUF2;
        const uint32_t klA = sb + (2 + cur) * TBUF2;
        const uint32_t vhA = sb + (4 + cur) * TBUF2;
        const uint32_t vlA = sb + (6 + cur) * TBUF2;

        float s[8][4];
#pragma unroll
        for (int nt = 0; nt < 8; nt++)
#pragma unroll
            for (int c = 0; c < 4; c++) s[nt][c] = 0.f;

#pragma unroll
        for (int ks = 0; ks < 4; ks++) {
#pragma unroll
            for (int npb = 0; npb < 4; npb++) {
                const uint32_t off = lrow[npb] + ks * 32;
                uint32_t bhf[4], blf[4];
                ldsm4(bhf, khA + off);
                ldsm4(blf, klA + off);
                mma_bf16(s[2 * npb],     qh[ks], bhf[0], bhf[1]);
                mma_bf16(s[2 * npb],     ql[ks], bhf[0], bhf[1]);
                mma_bf16(s[2 * npb],     qh[ks], blf[0], blf[1]);
                mma_bf16(s[2 * npb + 1], qh[ks], bhf[2], bhf[3]);
                mma_bf16(s[2 * npb + 1], ql[ks], bhf[2], bhf[3]);
                mma_bf16(s[2 * npb + 1], qh[ks], blf[2], blf[3]);
            }
        }

        float alpha[2];
#pragma unroll
        for (int h = 0; h < 2; h++) {
            float mx = -1e30f;
#pragma unroll
            for (int nt = 0; nt < 8; nt++)
                mx = fmaxf(mx, fmaxf(s[nt][2 * h], s[nt][2 * h + 1]));
            mx = fmaxf(mx, __shfl_xor_sync(0xffffffffu, mx, 1));
            mx = fmaxf(mx, __shfl_xor_sync(0xffffffffu, mx, 2));
            const float mnew = fmaxf(mi2[h], mx);
            alpha[h] = __expf(mi2[h] - mnew);
            float rs = 0.f;
#pragma unroll
            for (int nt = 0; nt < 8; nt++) {
                s[nt][2 * h]     = __expf(s[nt][2 * h]     - mnew);
                s[nt][2 * h + 1] = __expf(s[nt][2 * h + 1] - mnew);
                rs += s[nt][2 * h] + s[nt][2 * h + 1];
            }
            rs += __shfl_xor_sync(0xffffffffu, rs, 1);
            rs += __shfl_xor_sync(0xffffffffu, rs, 2);
            li[h] = li[h] * alpha[h] + rs;
            mi2[h] = mnew;
        }
#pragma unroll
        for (int nt = 0; nt < 8; nt++)
#pragma unroll
            for (int c = 0; c < 4; c++)
                o[nt][c] *= alpha[c >> 1];

#pragma unroll
        for (int j = 0; j < 4; j++) {
            uint32_t ah[4], al[4];
            split2(s[2 * j][0],     s[2 * j][1],     ah[0], al[0]);
            split2(s[2 * j][2],     s[2 * j][3],     ah[1], al[1]);
            split2(s[2 * j + 1][0], s[2 * j + 1][1], ah[2], al[2]);
            split2(s[2 * j + 1][2], s[2 * j + 1][3], ah[3], al[3]);
#pragma unroll
            for (int npb = 0; npb < 4; npb++) {
                const uint32_t off = lrow[npb] + j * 32;
                uint32_t vhf[4], vlf[4];
                ldsm4(vhf, vhA + off);
                ldsm4(vlf, vlA + off);
                mma_bf16(o[2 * npb],     ah, vhf[0], vhf[1]);
                mma_bf16(o[2 * npb],     al, vhf[0], vhf[1]);
                mma_bf16(o[2 * npb],     ah, vlf[0], vlf[1]);
                mma_bf16(o[2 * npb + 1], ah, vhf[2], vhf[3]);
                mma_bf16(o[2 * npb + 1], al, vhf[2], vhf[3]);
                mma_bf16(o[2 * npb + 1], ah, vlf[2], vlf[3]);
            }
        }
        __syncthreads();
    }

    // epilogue
    float* Ob = Og + ((size_t)bh * SEQ + q0) * HD;
#pragma unroll
    for (int h = 0; h < 2; h++) {
        const int row = m0 + grp + 8 * h;
        const float inv = 1.0f / li[h];
#pragma unroll
        for (int nt = 0; nt < 8; nt++) {
            const int d = nt * 8 + 2 * tig;
            float2 r;
            r.x = o[nt][2 * h]     * inv;
            r.y = o[nt][2 * h + 1] * inv;
            *(float2*)&Ob[(size_t)row * HD + d] = r;
        }
    }
}

// ---------------------------------------------------------------------------
extern "C" void kernel_launch(void* const* d_in, const int* in_sizes, int n_in,
                              void* d_out, int out_size)
{
    const float* q  = (const float*)d_in[0];
    const float* k  = (const float*)d_in[1];
    const float* v  = (const float*)d_in[2];
    const float* Wq = (const float*)d_in[3];
    const float* bq = (const float*)d_in[4];
    const float* Wk = (const float*)d_in[5];
    const float* bk = (const float*)d_in[6];
    const float* Wv = (const float*)d_in[7];
    const float* bv = (const float*)d_in[8];
    const float* Wo = (const float*)d_in[9];
    const float* bo = (const float*)d_in[10];
    float* out = (float*)d_out;

    float *Qb, *Ob;
    __nv_bfloat16 *Kh, *Kl, *Vth, *Vtl;
    cudaGetSymbolAddress((void**)&Qb, g_Q);
    cudaGetSymbolAddress((void**)&Ob, g_AO);
    cudaGetSymbolAddress((void**)&Kh, g_Kh);
    cudaGetSymbolAddress((void**)&Kl, g_Kl);
    cudaGetSymbolAddress((void**)&Vth, g_Vth);
    cudaGetSymbolAddress((void**)&Vtl, g_Vtl);

    cudaFuncSetAttribute(attn_bf16_kernel,
                         cudaFuncAttributeMaxDynamicSharedMemorySize, ATTN_SMEM_BYTES);

    dim3 blk(256);
    dim3 gProj(DM / 128, TOK / 128);   // (8, 64)

    tgemm_kernel<0, 1><<<gProj, blk>>>(q, Wq, bq, Qb, nullptr, nullptr, TOK, DM, DM);
    tgemm_kernel<0, 2><<<gProj, blk>>>(k, Wk, bk, nullptr, Kh, Kl, TOK, DM, DM);
    tgemm_kernel<0, 3><<<gProj, blk>>>(v, Wv, bv, nullptr, Vth, Vtl, TOK, DM, DM);

    attn_bf16_kernel<<<dim3(SEQ / 64, BHN), dim3(128), ATTN_SMEM_BYTES>>>(
        Qb, Kh, Kl, Vth, Vtl, Ob);

    tgemm_kernel<1, 0><<<gProj, blk>>>(Ob, Wo, bo, out, nullptr, nullptr, TOK, DM, DM);
}